// round 8
// baseline (speedup 1.0000x reference)
#include <cuda_runtime.h>
#include <math_constants.h>

#define BSZ      1024
#define KCOLS    66560              // BSZ + 65536
#define KV4      (KCOLS / 4)        // 16640 float4 per row (fallback path)
#define KV8      (KCOLS / 8)        // 8320 float8 per row
#define NTHREADS 256
#define NWARPS   (NTHREADS / 32)
#define NITER    16                 // 16 iters x 2 float8 = 32 float8/thread
#define VCAP8    768                // captured float8 slots (expect ~400 used)
#define TCAND    2.5f

__device__ float    g_row_loss[BSZ];
__device__ unsigned g_done = 0;     // reset by last block each launch -> replay-safe

#define LDG256(r, p)                                                            \
    asm volatile("ld.global.v8.f32 {%0,%1,%2,%3,%4,%5,%6,%7}, [%8];"            \
        : "=f"((r)[0]), "=f"((r)[1]), "=f"((r)[2]), "=f"((r)[3]),               \
          "=f"((r)[4]), "=f"((r)[5]), "=f"((r)[6]), "=f"((r)[7])                \
        : "l"(p))

__global__ __launch_bounds__(NTHREADS, 7) void wl_row_kernel(const float* __restrict__ logits,
                                                             float* __restrict__ out)
{
    const int row = blockIdx.x;
    const float* __restrict__ rowp = logits + (size_t)row * KCOLS;

    __shared__ __align__(16) float s_vc8[VCAP8][8];   // captured float8s (24 KB)
    __shared__ int   s_vi8[VCAP8];                    // their float8 indices (3 KB)
    __shared__ int   s_cnt;
    __shared__ float s_sum[NWARPS];
    __shared__ float s_max[NWARPS];
    __shared__ float s_par[4];                        // inv, m, dl, fast-flag
    __shared__ int   s_last;

    const int tid = threadIdx.x;
    if (tid == 0) s_cnt = 0;
    __syncthreads();

    // ---- Pass 1: 2x LDG.256 per iter; 1 capture branch per 16 elements --------
    float a0 = 0.f, a1 = 0.f, a2 = 0.f, a3 = 0.f;

    #define WL_EXP8(r)                                                          \
        { a0 += __expf((r)[0]); a1 += __expf((r)[1]);                           \
          a2 += __expf((r)[2]); a3 += __expf((r)[3]);                           \
          a0 += __expf((r)[4]); a1 += __expf((r)[5]);                           \
          a2 += __expf((r)[6]); a3 += __expf((r)[7]); }
    #define WL_MAX8(r)                                                          \
        fmaxf(fmaxf(fmaxf((r)[0], (r)[1]), fmaxf((r)[2], (r)[3])),              \
              fmaxf(fmaxf((r)[4], (r)[5]), fmaxf((r)[6], (r)[7])))
    #define WL_PUSH8(r, VIDX)                                                   \
        { int p = atomicAdd(&s_cnt, 1);                                         \
          if (p < VCAP8) {                                                      \
              ((float4*)s_vc8[p])[0] = make_float4((r)[0], (r)[1], (r)[2], (r)[3]); \
              ((float4*)s_vc8[p])[1] = make_float4((r)[4], (r)[5], (r)[6], (r)[7]); \
              s_vi8[p] = (VIDX);                                                \
          } }

    #pragma unroll 1
    for (int it = 0; it < NITER; it++) {
        const int va = tid + it * (2 * NTHREADS);
        const int vb = va + NTHREADS;
        float ra[8], rb[8];
        LDG256(ra, rowp + (size_t)va * 8);      // two back-to-back 256-bit loads
        LDG256(rb, rowp + (size_t)vb * 8);

        WL_EXP8(ra)
        WL_EXP8(rb)

        float mxa = WL_MAX8(ra);
        float mxb = WL_MAX8(rb);
        if (fmaxf(mxa, mxb) >= TCAND) {         // rare: ~4.6% of iterations
            if (mxa >= TCAND) WL_PUSH8(ra, va)
            if (mxb >= TCAND) WL_PUSH8(rb, vb)
        }
    }
    if (tid < 128) {                            // remainder: 128 float8s
        const int v = 32 * NTHREADS + tid;      // 8192 + tid < 8320
        float r[8];
        LDG256(r, rowp + (size_t)v * 8);
        WL_EXP8(r)
        if (WL_MAX8(r) >= TCAND) WL_PUSH8(r, v)
    }
    #undef WL_EXP8
    #undef WL_MAX8
    #undef WL_PUSH8

    float sum = (a0 + a1) + (a2 + a3);
    #pragma unroll
    for (int o = 16; o; o >>= 1) sum += __shfl_xor_sync(0xffffffffu, sum, o);
    if ((tid & 31) == 0) s_sum[tid >> 5] = sum;
    __syncthreads();

    // ---- Filter stage (smem-only): exact off-diag max over true candidates ----
    const int ncv = min(s_cnt, VCAP8);
    float mxo = -CUDART_INF_F;
    for (int i = tid; i < ncv; i += NTHREADS) {
        const int base = s_vi8[i] * 8;
        #pragma unroll
        for (int q = 0; q < 8; q++) {
            float xv = s_vc8[i][q];
            if (xv >= TCAND && base + q != row) mxo = fmaxf(mxo, xv);
        }
    }
    #pragma unroll
    for (int o = 16; o; o >>= 1) mxo = fmaxf(mxo, __shfl_xor_sync(0xffffffffu, mxo, o));
    if ((tid & 31) == 0) s_max[tid >> 5] = mxo;
    __syncthreads();

    if (tid == 0) {
        float S = 0.f, M = -CUDART_INF_F;
        #pragma unroll
        for (int i = 0; i < NWARPS; i++) { S += s_sum[i]; M = fmaxf(M, s_max[i]); }
        float dl       = rowp[row];                              // cache hit
        float neg_mean = (S - __expf(dl)) * (1.0f / (float)(KCOLS - 1));
        float inv      = 1.0f / neg_mean;
        // g(l)=l*exp(l)*inv monotone for l >= -1; M >= TCAND > 0 on fast path, so
        // g(M) is the EXACT off-diagonal max of u. Row max m = max(g(M), dl).
        float gmo = M * __expf(M) * inv;
        float m   = fmaxf(gmo, dl);
        float gT  = TCAND * __expf(TCAND) * inv;  // bound on any non-candidate u
        bool fast = (M >= TCAND) && (neg_mean > 0.f) &&
                    (gT <= m - 30.f) && (s_cnt <= VCAP8);
        s_par[0] = inv; s_par[1] = m; s_par[2] = dl; s_par[3] = fast ? 1.f : 0.f;
    }
    __syncthreads();

    const float inv = s_par[0], m = s_par[1], dl = s_par[2];
    const bool  fast = (s_par[3] != 0.f);

    if (fast) {
        // ---- Pass 2 (fast): filtered candidates from smem — zero re-read -------
        float sl = 0.f;
        for (int i = tid; i < ncv; i += NTHREADS) {
            const int base = s_vi8[i] * 8;
            #pragma unroll
            for (int q = 0; q < 8; q++) {
                float xv = s_vc8[i][q];
                if (xv >= TCAND && base + q != row)
                    sl += __expf(xv * __expf(xv) * inv - m);
            }
        }
        #pragma unroll
        for (int o = 16; o; o >>= 1) sl += __shfl_xor_sync(0xffffffffu, sl, o);
        if ((tid & 31) == 0) s_sum[tid >> 5] = sl;
        __syncthreads();
        if (tid == 0) {
            float s = __expf(dl - m);             // diagonal term (u_ii = dl)
            #pragma unroll
            for (int i = 0; i < NWARPS; i++) s += s_sum[i];
            g_row_loss[row] = m + logf(s) - dl;
        }
    } else {
        // ---- Pass 2 (robust fallback): full online-LSE re-read ------------------
        const float4* __restrict__ rp = reinterpret_cast<const float4*>(rowp);
        float mt = -CUDART_INF_F, st = 0.f;
        for (int v = tid; v < KV4; v += NTHREADS) {
            float4 x = rp[v];
            float c[4] = {x.x, x.y, x.z, x.w};
            #pragma unroll
            for (int q = 0; q < 4; q++) {
                int   j = v * 4 + q;
                float u = (j == row) ? dl : c[q] * __expf(c[q]) * inv;
                float nm = fmaxf(mt, u);
                st = st * __expf(mt - nm) + __expf(u - nm);
                mt = nm;
            }
        }
        #pragma unroll
        for (int o = 16; o; o >>= 1) {
            float om = __shfl_xor_sync(0xffffffffu, mt, o);
            float os = __shfl_xor_sync(0xffffffffu, st, o);
            float nm = fmaxf(mt, om);
            st = st * __expf(mt - nm) + os * __expf(om - nm);
            mt = nm;
        }
        if ((tid & 31) == 0) { s_sum[tid >> 5] = st; s_max[tid >> 5] = mt; }
        __syncthreads();
        if (tid == 0) {
            float m2 = -CUDART_INF_F, s2v = 0.f;
            #pragma unroll
            for (int i = 0; i < NWARPS; i++) m2 = fmaxf(m2, s_max[i]);
            #pragma unroll
            for (int i = 0; i < NWARPS; i++) s2v += s_sum[i] * __expf(s_max[i] - m2);
            g_row_loss[row] = m2 + logf(s2v) - dl;
        }
    }

    // ---- Fused final reduction: last finishing block sums the 1024 row losses --
    if (tid == 0) {
        __threadfence();
        unsigned t = atomicAdd(&g_done, 1u);
        s_last = (t == (unsigned)(gridDim.x - 1));
    }
    __syncthreads();
    if (s_last) {
        float v = 0.f;
        #pragma unroll
        for (int i = tid; i < BSZ; i += NTHREADS) v += __ldcg(&g_row_loss[i]);
        #pragma unroll
        for (int o = 16; o; o >>= 1) v += __shfl_xor_sync(0xffffffffu, v, o);
        if ((tid & 31) == 0) s_sum[tid >> 5] = v;
        __syncthreads();
        if (tid == 0) {
            float t = 0.f;
            #pragma unroll
            for (int i = 0; i < NWARPS; i++) t += s_sum[i];
            out[0] = t * (1.0f / (float)BSZ);
            g_done = 0;                           // reset for next graph replay
        }
    }
}

extern "C" void kernel_launch(void* const* d_in, const int* in_sizes, int n_in,
                              void* d_out, int out_size)
{
    const float* logits = (const float*)d_in[0];
    (void)in_sizes; (void)n_in; (void)out_size;
    wl_row_kernel<<<BSZ, NTHREADS>>>(logits, (float*)d_out);
}